// round 1
// baseline (speedup 1.0000x reference)
#include <cuda_runtime.h>
#include <cstdint>
#include <cstddef>

#define TSIZE (1u << 18)
#define TMASK (TSIZE - 1u)
#define NLEV 16

// Feature-interleaved scratch tables (device globals: no allocation).
__device__ float2 g_hash[15u * TSIZE];   // 15 levels * 2^18 entries * 8B = 31.5 MB
__device__ float2 g_dense[16 * 16 * 16]; // 32 KB

// ---------------------------------------------------------------------------
// Repack: [F, T] -> [T, F] (float2) so each corner gather is one 8B load.
// ---------------------------------------------------------------------------
__global__ void repack_kernel(const float* __restrict__ dense,
                              const float* __restrict__ hash) {
    unsigned i = blockIdx.x * blockDim.x + threadIdx.x;
    if (i < 15u * TSIZE) {
        unsigned l = i >> 18;
        unsigned t = i & TMASK;
        const float* base = hash + (size_t)l * (2u * TSIZE);
        g_hash[i] = make_float2(base[t], base[TSIZE + t]);
    }
    if (i < 4096u) {
        g_dense[i] = make_float2(dense[i], dense[4096u + i]);
    }
}

// ---------------------------------------------------------------------------
// Main encoding kernel: one thread per point, all 16 levels unrolled.
// ---------------------------------------------------------------------------
__global__ __launch_bounds__(256)
void encode_kernel(const float* __restrict__ coords,
                   float* __restrict__ out, int N) {
    int i = blockIdx.x * blockDim.x + threadIdx.x;
    if (i >= N) return;

    const float cx = __ldg(&coords[3 * i + 0]);
    const float cy = __ldg(&coords[3 * i + 1]);
    const float cz = __ldg(&coords[3 * i + 2]);

    float4* __restrict__ out4 = reinterpret_cast<float4*>(out + (size_t)i * 32);

    constexpr int RES[NLEV] = {16, 20, 25, 32, 40, 50, 64, 80,
                               101, 128, 161, 203, 256, 322, 406, 512};

    float4 obuf = make_float4(0.f, 0.f, 0.f, 0.f);

#pragma unroll
    for (int l = 0; l < NLEV; ++l) {
        const int res = RES[l];
        const float rm1 = (float)(res - 1);

        // pos = clip((c + 1) * 0.5 * (res-1), 0, res-1)  -- same op order as ref
        float px = fminf(fmaxf((cx + 1.0f) * 0.5f * rm1, 0.0f), rm1);
        float py = fminf(fmaxf((cy + 1.0f) * 0.5f * rm1, 0.0f), rm1);
        float pz = fminf(fmaxf((cz + 1.0f) * 0.5f * rm1, 0.0f), rm1);

        int ix0 = (int)px;  float wx = px - (float)ix0;
        int iy0 = (int)py;  float wy = py - (float)iy0;
        int iz0 = (int)pz;  float wz = pz - (float)iz0;
        int ix1 = min(ix0 + 1, res - 1);
        int iy1 = min(iy0 + 1, res - 1);
        int iz1 = min(iz0 + 1, res - 1);

        float wxv0 = 1.0f - wx, wxv1 = wx;
        float wyv0 = 1.0f - wy, wyv1 = wy;
        float wzv0 = 1.0f - wz, wzv1 = wz;

        float2 f[8];
        float  wg[8];

        if (l == 0) {
            // Dense level: flat = (x*16 + y)*16 + z
#pragma unroll
            for (int c = 0; c < 8; ++c) {
                const int xi = (c & 4) ? ix1 : ix0;
                const int yi = (c & 2) ? iy1 : iy0;
                const int zi = (c & 1) ? iz1 : iz0;
                f[c] = __ldg(&g_dense[(xi * 16 + yi) * 16 + zi]);
                wg[c] = ((c & 4) ? wxv1 : wxv0) *
                        ((c & 2) ? wyv1 : wyv0) *
                        ((c & 1) ? wzv1 : wzv0);
            }
        } else {
            const float2* __restrict__ tbl = g_hash + (size_t)(l - 1) * TSIZE;
            const unsigned hx0 = (unsigned)ix0;                 // prime 1
            const unsigned hx1 = (unsigned)ix1;
            const unsigned hy0 = (unsigned)iy0 * 2654435761u;
            const unsigned hy1 = (unsigned)iy1 * 2654435761u;
            const unsigned hz0 = (unsigned)iz0 * 805459861u;
            const unsigned hz1 = (unsigned)iz1 * 805459861u;
#pragma unroll
            for (int c = 0; c < 8; ++c) {
                const unsigned h = (((c & 4) ? hx1 : hx0) ^
                                    ((c & 2) ? hy1 : hy0) ^
                                    ((c & 1) ? hz1 : hz0)) & TMASK;
                f[c] = __ldg(&tbl[h]);
                wg[c] = ((c & 4) ? wxv1 : wxv0) *
                        ((c & 2) ? wyv1 : wyv0) *
                        ((c & 1) ? wzv1 : wzv0);
            }
        }

        float a0 = 0.0f, a1 = 0.0f;
#pragma unroll
        for (int c = 0; c < 8; ++c) {
            a0 = fmaf(f[c].x, wg[c], a0);
            a1 = fmaf(f[c].y, wg[c], a1);
        }

        if ((l & 1) == 0) {
            obuf.x = a0; obuf.y = a1;
        } else {
            obuf.z = a0; obuf.w = a1;
            out4[l >> 1] = obuf;   // full 16B store; 8 of these fill the 128B row
        }
    }
}

// ---------------------------------------------------------------------------
// kernel_launch: repack (streaming, ~10us) then encode.
// ---------------------------------------------------------------------------
extern "C" void kernel_launch(void* const* d_in, const int* in_sizes, int n_in,
                              void* d_out, int out_size) {
    const float* coords = (const float*)d_in[0];
    const float* dense  = (const float*)d_in[1];
    const float* hash   = (const float*)d_in[2];
    float* out = (float*)d_out;

    const int N = in_sizes[0] / 3;

    const unsigned repack_total = 15u * TSIZE;
    repack_kernel<<<(repack_total + 255u) / 256u, 256>>>(dense, hash);
    encode_kernel<<<(N + 255) / 256, 256>>>(coords, out, N);
}